// round 11
// baseline (speedup 1.0000x reference)
#include <cuda_runtime.h>
#include <cstdint>
#include <cstddef>

#define IN_F   8192
#define OUT_F  8192
#define BATCH  32
#define KSPLIT 16
#define KCHUNK (IN_F / KSPLIT)     // 512
#define NIT    (KCHUNK / 32)       // 16 k32 steps per CTA
#define MTILE  128                 // rows per CTA (8 warps x 16 rows)
#define THREADS 256
#define NS32   (IN_F / 32)         // 256 global k32 steps

#define STAGES      4
#define STAGE_BYTES (MTILE * 128)            // 16 KB: 128 rows x 32 ints
#define SMEM_B_OFF  (STAGES * STAGE_BYTES)   // 65536
#define SMEM_TOTAL  (SMEM_B_OFF + NIT * 2048) // 98304

#define S0 0.0625f                 // 2^-4
#define S1 0.00048828125f          // 2^-11

// B planes in s8 fragment order. uint2 index: (s*8 + j)*32 + g*4 + t
__device__ uint32_t g_xbq[(size_t)NS32 * 256 * 2];               // 512 KB
__device__ float g_partial[(size_t)KSPLIT * OUT_F * BATCH];      // 16 MB

// ---- helpers -----------------------------------------------------------------
__device__ __forceinline__ uint32_t smem_u32(const void* p) {
    uint32_t a;
    asm("{ .reg .u64 t; cvta.to.shared.u64 t, %1; cvt.u32.u64 %0, t; }" : "=r"(a) : "l"(p));
    return a;
}
__device__ __forceinline__ uint32_t prmt(uint32_t a, uint32_t b, uint32_t sel) {
    uint32_t d;
    asm("prmt.b32 %0, %1, %2, %3;" : "=r"(d) : "r"(a), "r"(b), "r"(sel));
    return d;
}
__device__ __forceinline__ uint32_t pack_s8(int4 w) {
    uint32_t lo = prmt((uint32_t)w.x, (uint32_t)w.y, 0x0040);
    uint32_t hi = prmt((uint32_t)w.z, (uint32_t)w.w, 0x0040);
    return prmt(lo, hi, 0x5410);
}
__device__ __forceinline__ void imma16832(int* d, uint32_t a0, uint32_t a1,
                                          uint32_t a2, uint32_t a3,
                                          uint32_t b0, uint32_t b1) {
    asm volatile(
        "mma.sync.aligned.m16n8k32.row.col.s32.s8.s8.s32 "
        "{%0,%1,%2,%3}, {%4,%5,%6,%7}, {%8,%9}, {%0,%1,%2,%3};"
        : "+r"(d[0]), "+r"(d[1]), "+r"(d[2]), "+r"(d[3])
        : "r"(a0), "r"(a1), "r"(a2), "r"(a3), "r"(b0), "r"(b1));
}
__device__ __forceinline__ int q8(float v, float mul, float lim) {
    float q = rintf(v * mul);
    q = fminf(fmaxf(q, -lim), lim);
    return (int)q;
}

// ---- Kernel 1: x[32][8192] f32 -> two s8 planes in fragment order ------------
__global__ void xprep_kernel(const float* __restrict__ x) {
    int gidx = blockIdx.x * blockDim.x + threadIdx.x;   // 65536 threads
    int b  = gidx >> 11;
    int k4 = gidx & 2047;
    int k0 = k4 * 4;
    float4 v = ((const float4*)(x + (size_t)b * IN_F))[k4];

    int q0[4], q1[4];
    float xs[4] = {v.x, v.y, v.z, v.w};
#pragma unroll
    for (int i = 0; i < 4; i++) {
        q0[i] = q8(xs[i], 16.0f, 127.0f);
        float r = xs[i] - (float)q0[i] * S0;
        q1[i] = q8(r, 2048.0f, 127.0f);
    }
    uint32_t p0 = (uint32_t)(q0[0] & 0xFF) | ((uint32_t)(q0[1] & 0xFF) << 8) |
                  ((uint32_t)(q0[2] & 0xFF) << 16) | ((uint32_t)(q0[3] & 0xFF) << 24);
    uint32_t p1 = (uint32_t)(q1[0] & 0xFF) | ((uint32_t)(q1[1] & 0xFF) << 8) |
                  ((uint32_t)(q1[2] & 0xFF) << 16) | ((uint32_t)(q1[3] & 0xFF) << 24);

    int s = k0 >> 5;
    int q = k0 & 31;
    int t = (q & 15) >> 2;
    int h = q >> 4;

    int j0 = b >> 3, g0 = b & 7;
    size_t i0 = ((size_t)(s * 8 + j0)     * 32 + g0 * 4 + t) * 2 + h;
    size_t i1 = ((size_t)(s * 8 + j0 + 4) * 32 + g0 * 4 + t) * 2 + h;
    g_xbq[i0] = p0;
    g_xbq[i1] = p1;
}

// ---- Kernel 2: s8 IMMA GEMM, weights streamed via cp.async pipeline ----------
// grid=(64,16)=1024 CTAs, occ 2 (16 warps/SM). 3 stages (48 KB/CTA) in flight
// through LDGSTS -> no LDG line-cap; target full LTS bandwidth.
__global__ void __launch_bounds__(THREADS, 2)
gemm_kernel(const int* __restrict__ W) {
    extern __shared__ char smem[];
    const uint32_t sA = smem_u32(smem);

    const int tid  = threadIdx.x;
    const int lane = tid & 31;
    const int warp = tid >> 5;                          // 0..7
    const int g    = lane >> 2;                         // 0..7
    const int t    = lane & 3;                          // 0..3

    const int rowbase = blockIdx.x * MTILE;             // CTA row base
    const int kbase   = blockIdx.y * KCHUNK;
    const int sbase   = kbase >> 5;

    // Stage B slice (contiguous 32 KB of g_xbq) into smem, coalesced LDG/STS.
    uint2* __restrict__ sB = (uint2*)(smem + SMEM_B_OFF);
    {
        const uint4* __restrict__ src =
            (const uint4*)(((const uint2*)g_xbq) + (size_t)sbase * 256);
        uint4* dst = (uint4*)sB;
#pragma unroll
        for (int i = tid; i < NIT * 128; i += THREADS) dst[i] = src[i];
    }

    // cp.async stage issue: 1024 16-B chunks per stage, 4 per thread.
    // smem layout: row*128 + (chunk ^ (row&7))*16  (XOR-swizzle, conflict-free LDS)
#define ISSUE(it_)                                                              \
    do {                                                                        \
        const uint32_t bs = sA + (((it_) & 3) * STAGE_BYTES);                   \
        const int kk = kbase + (it_) * 32;                                      \
        _Pragma("unroll")                                                       \
        for (int q2 = 0; q2 < 4; q2++) {                                        \
            int cid = tid + 256 * q2;                                           \
            int row = cid >> 3;                                                 \
            int c   = cid & 7;                                                  \
            uint32_t ds = bs + row * 128 + ((c ^ (row & 7)) << 4);              \
            const int* sp = W + (size_t)(rowbase + row) * IN_F + kk + c * 4;    \
            asm volatile("cp.async.cg.shared.global [%0], [%1], 16;"            \
                         :: "r"(ds), "l"(sp));                                  \
        }                                                                       \
        asm volatile("cp.async.commit_group;");                                 \
    } while (0)

    int acc[8][4];
#pragma unroll
    for (int j = 0; j < 8; j++)
#pragma unroll
        for (int e = 0; e < 4; e++) acc[j][e] = 0;

    ISSUE(0); ISSUE(1); ISSUE(2);

    const int r0 = warp * 16 + g;                       // local row (g&7 == g)

#define STEP(it_, WN, DOISSUE)                                                  \
    do {                                                                        \
        asm volatile("cp.async.wait_group %0;" :: "n"(WN));                     \
        __syncthreads();                                                        \
        if (DOISSUE) ISSUE((it_) + 3);                                          \
        const char* ab = smem + (((it_) & 3) * STAGE_BYTES);                    \
        int4 wa0 = *(const int4*)(ab + (r0    ) * 128 + (( t      ^ g) << 4));  \
        int4 wa1 = *(const int4*)(ab + (r0 + 8) * 128 + (( t      ^ g) << 4));  \
        int4 wa2 = *(const int4*)(ab + (r0    ) * 128 + (((t + 4) ^ g) << 4));  \
        int4 wa3 = *(const int4*)(ab + (r0 + 8) * 128 + (((t + 4) ^ g) << 4));  \
        uint32_t A0 = pack_s8(wa0);                                             \
        uint32_t A1 = pack_s8(wa1);                                             \
        uint32_t A2 = pack_s8(wa2);                                             \
        uint32_t A3 = pack_s8(wa3);                                             \
        const uint2* __restrict__ bp = sB + (it_) * 256 + g * 4 + t;            \
        _Pragma("unroll")                                                       \
        for (int j = 0; j < 8; j++) {                                           \
            uint2 bv = bp[j * 32];                                              \
            imma16832(acc[j], A0, A1, A2, A3, bv.x, bv.y);                      \
        }                                                                       \
    } while (0)

#pragma unroll 1
    for (int it = 0; it < NIT - 3; ++it) STEP(it, 2, true);
    STEP(NIT - 3, 2, false);
    STEP(NIT - 2, 1, false);
    STEP(NIT - 1, 0, false);

#undef STEP
#undef ISSUE

    // Epilogue: out = S0*plane0 (j<4) + S1*plane1 (j+4); store f32 partials.
    float* pk = g_partial + (size_t)blockIdx.y * OUT_F * BATCH;
    const int rg = rowbase + warp * 16 + g;
#pragma unroll
    for (int j = 0; j < 4; j++) {
        const int n0 = 8 * j + 2 * t;
        float2 v0, v1;
        v0.x = S0 * (float)acc[j][0] + S1 * (float)acc[j + 4][0];
        v0.y = S0 * (float)acc[j][1] + S1 * (float)acc[j + 4][1];
        v1.x = S0 * (float)acc[j][2] + S1 * (float)acc[j + 4][2];
        v1.y = S0 * (float)acc[j][3] + S1 * (float)acc[j + 4][3];
        *(float2*)(pk + (size_t)rg * BATCH + n0)       = v0;
        *(float2*)(pk + (size_t)(rg + 8) * BATCH + n0) = v1;
    }
}

// ---- Kernel 3: reduce k-splits, apply softplus scale + bias -----------------
__global__ void reduce_kernel(const float* __restrict__ log_scale,
                              const float* __restrict__ bias,
                              float* __restrict__ out) {
    int g  = blockIdx.x * blockDim.x + threadIdx.x;
    int o  = g >> 3;
    int bq = g & 7;

    const float4* __restrict__ base = (const float4*)g_partial;
    float4 s = make_float4(0.f, 0.f, 0.f, 0.f);
#pragma unroll
    for (int ky = 0; ky < KSPLIT; ky++) {
        float4 p = base[((size_t)ky * OUT_F + o) * (BATCH / 4) + bq];
        s.x += p.x; s.y += p.y; s.z += p.z; s.w += p.w;
    }

    float ls = log_scale[o];
    float sp = (ls > 20.0f) ? ls : log1pf(expf(ls));
    float sc = fmaxf(sp, 1e-4f);
    float bi = bias[o];

    int b0 = bq << 2;
    out[(size_t)(b0 + 0) * OUT_F + o] = fmaf(sc, s.x, bi);
    out[(size_t)(b0 + 1) * OUT_F + o] = fmaf(sc, s.y, bi);
    out[(size_t)(b0 + 2) * OUT_F + o] = fmaf(sc, s.z, bi);
    out[(size_t)(b0 + 3) * OUT_F + o] = fmaf(sc, s.w, bi);
}

// ---- Launch ------------------------------------------------------------------
extern "C" void kernel_launch(void* const* d_in, const int* in_sizes, int n_in,
                              void* d_out, int out_size) {
    const float* x  = nullptr;
    const int*   W  = nullptr;
    const float* ls = nullptr;
    const float* bi = nullptr;
    for (int i = 0; i < n_in; i++) {
        long long sz = in_sizes[i];
        if (sz == (long long)OUT_F * IN_F)      W = (const int*)d_in[i];
        else if (sz == (long long)BATCH * IN_F) x = (const float*)d_in[i];
        else if (sz == OUT_F) {
            if (!ls) ls = (const float*)d_in[i];
            else     bi = (const float*)d_in[i];
        }
    }
    float* out = (float*)d_out;

    cudaFuncSetAttribute(gemm_kernel, cudaFuncAttributeMaxDynamicSharedMemorySize,
                         SMEM_TOTAL);

    xprep_kernel<<<(BATCH * IN_F / 4) / 128, 128>>>(x);

    dim3 grid(OUT_F / MTILE, KSPLIT);            // (64, 16) = 1024 CTAs
    gemm_kernel<<<grid, THREADS, SMEM_TOTAL>>>(W);

    reduce_kernel<<<(OUT_F * BATCH / 4) / 256, 256>>>(ls, bi, out);
}

// round 12
// speedup vs baseline: 1.0086x; 1.0086x over previous
#include <cuda_runtime.h>
#include <cstdint>
#include <cstddef>

#define IN_F   8192
#define OUT_F  8192
#define BATCH  32
#define KSPLIT 16
#define KCHUNK (IN_F / KSPLIT)     // 512 ints = 2 KB per row per CTA
#define MTILE  64                  // rows per CTA (4 warps x 16 rows)
#define THREADS 128
#define MEGA   4                   // mega-stages per CTA (k128 each)
#define STAGE_BYTES (MTILE * 512)  // 64 rows x 512 B = 32 KB
#define SMEM_TOTAL  (2 * STAGE_BYTES)
#define NS32   (IN_F / 32)         // 256 global k32 steps

#define S0 0.0625f                 // 2^-4
#define S1 0.00048828125f          // 2^-11

// B planes in s8 fragment order. uint2 index: (s*8 + j)*32 + g*4 + t
__device__ uint32_t g_xbq[(size_t)NS32 * 256 * 2];               // 512 KB
__device__ float g_partial[(size_t)KSPLIT * OUT_F * BATCH];      // 16 MB

// ---- helpers -----------------------------------------------------------------
__device__ __forceinline__ uint32_t smem_u32(const void* p) {
    uint32_t a;
    asm("{ .reg .u64 t; cvta.to.shared.u64 t, %1; cvt.u32.u64 %0, t; }" : "=r"(a) : "l"(p));
    return a;
}
__device__ __forceinline__ uint32_t prmt(uint32_t a, uint32_t b, uint32_t sel) {
    uint32_t d;
    asm("prmt.b32 %0, %1, %2, %3;" : "=r"(d) : "r"(a), "r"(b), "r"(sel));
    return d;
}
__device__ __forceinline__ uint32_t pack_s8(int4 w) {
    uint32_t lo = prmt((uint32_t)w.x, (uint32_t)w.y, 0x0040);
    uint32_t hi = prmt((uint32_t)w.z, (uint32_t)w.w, 0x0040);
    return prmt(lo, hi, 0x5410);
}
__device__ __forceinline__ void imma16832(int* d, uint32_t a0, uint32_t a1,
                                          uint32_t a2, uint32_t a3,
                                          uint32_t b0, uint32_t b1) {
    asm volatile(
        "mma.sync.aligned.m16n8k32.row.col.s32.s8.s8.s32 "
        "{%0,%1,%2,%3}, {%4,%5,%6,%7}, {%8,%9}, {%0,%1,%2,%3};"
        : "+r"(d[0]), "+r"(d[1]), "+r"(d[2]), "+r"(d[3])
        : "r"(a0), "r"(a1), "r"(a2), "r"(a3), "r"(b0), "r"(b1));
}
__device__ __forceinline__ int q8(float v, float mul, float lim) {
    float q = rintf(v * mul);
    q = fminf(fmaxf(q, -lim), lim);
    return (int)q;
}

// ---- Kernel 1: x[32][8192] f32 -> two s8 planes in fragment order ------------
__global__ void xprep_kernel(const float* __restrict__ x) {
    int gidx = blockIdx.x * blockDim.x + threadIdx.x;   // 65536 threads
    int b  = gidx >> 11;
    int k4 = gidx & 2047;
    int k0 = k4 * 4;
    float4 v = ((const float4*)(x + (size_t)b * IN_F))[k4];

    int q0[4], q1[4];
    float xs[4] = {v.x, v.y, v.z, v.w};
#pragma unroll
    for (int i = 0; i < 4; i++) {
        q0[i] = q8(xs[i], 16.0f, 127.0f);
        float r = xs[i] - (float)q0[i] * S0;
        q1[i] = q8(r, 2048.0f, 127.0f);
    }
    uint32_t p0 = (uint32_t)(q0[0] & 0xFF) | ((uint32_t)(q0[1] & 0xFF) << 8) |
                  ((uint32_t)(q0[2] & 0xFF) << 16) | ((uint32_t)(q0[3] & 0xFF) << 24);
    uint32_t p1 = (uint32_t)(q1[0] & 0xFF) | ((uint32_t)(q1[1] & 0xFF) << 8) |
                  ((uint32_t)(q1[2] & 0xFF) << 16) | ((uint32_t)(q1[3] & 0xFF) << 24);

    int s = k0 >> 5;
    int q = k0 & 31;
    int t = (q & 15) >> 2;
    int h = q >> 4;

    int j0 = b >> 3, g0 = b & 7;
    size_t i0 = ((size_t)(s * 8 + j0)     * 32 + g0 * 4 + t) * 2 + h;
    size_t i1 = ((size_t)(s * 8 + j0 + 4) * 32 + g0 * 4 + t) * 2 + h;
    g_xbq[i0] = p0;
    g_xbq[i1] = p1;
}

// ---- Kernel 2: s8 IMMA GEMM, 512-B-burst cp.async weight stream --------------
// grid=(128,16)=2048 CTAs, occ 3 (12 warps/SM). Each cp.async warp-instruction
// reads one FULL 512-B row segment (contiguous) -> DRAM row-buffer friendly.
__global__ void __launch_bounds__(THREADS, 3)
gemm_kernel(const int* __restrict__ W) {
    extern __shared__ char smem[];
    const uint32_t sA = smem_u32(smem);

    const int tid  = threadIdx.x;
    const int lane = tid & 31;
    const int warp = tid >> 5;                          // 0..3
    const int g    = lane >> 2;                         // 0..7
    const int t    = lane & 3;                          // 0..3

    const int rowbase = blockIdx.x * MTILE;
    const int kbase   = blockIdx.y * KCHUNK;
    const int sbase   = kbase >> 5;                     // global k32 step base

    // Issue one mega-stage (64 rows x 512 B). Warp covers rows warp+4q fully:
    // each cp.async instruction = 32 lanes x 16 B = 512 B contiguous burst.
#define ISSUE(ms_)                                                              \
    do {                                                                        \
        const uint32_t bs = sA + (((ms_) & 1) * STAGE_BYTES);                   \
        const int kk = kbase + (ms_) * 128;                                     \
        _Pragma("unroll")                                                       \
        for (int q2 = 0; q2 < 16; q2++) {                                       \
            int row = warp + 4 * q2;                                            \
            uint32_t ds = bs + row * 512 + (((lane ^ (row & 7)) & 31) << 4);    \
            const int* sp = W + (size_t)(rowbase + row) * IN_F + kk + lane * 4; \
            asm volatile("cp.async.cg.shared.global [%0], [%1], 16;"            \
                         :: "r"(ds), "l"(sp));                                  \
        }                                                                       \
        asm volatile("cp.async.commit_group;");                                 \
    } while (0)

    // B fragment prefetch (L2-hot, 512 KB total reused by 128 M-tiles).
    uint2 cb[8], nb[8];
#define LOADB(dst, fs_)                                                         \
    do {                                                                        \
        const uint2* _p = ((const uint2*)g_xbq) +                               \
            ((size_t)(sbase + (fs_)) * 8) * 32 + g * 4 + t;                     \
        _Pragma("unroll")                                                       \
        for (int j = 0; j < 8; j++) dst[j] = _p[j * 32];                        \
    } while (0)

    int acc[8][4];
#pragma unroll
    for (int j = 0; j < 8; j++)
#pragma unroll
        for (int e = 0; e < 4; e++) acc[j][e] = 0;

    ISSUE(0);
    ISSUE(1);
    LOADB(cb, 0);

    const int R0 = warp * 16 + g;                       // stage-local row
    const uint32_t swz = (uint32_t)g;                   // (R0&7)==(R0+8)&7==g

#pragma unroll
    for (int ms = 0; ms < MEGA; ++ms) {
        if (ms < MEGA - 1) asm volatile("cp.async.wait_group 1;");
        else               asm volatile("cp.async.wait_group 0;");
        __syncthreads();

        const char* ab = smem + ((ms & 1) * STAGE_BYTES);
#pragma unroll
        for (int s = 0; s < 4; s++) {
            const int fs = ms * 4 + s;
            if (fs + 1 < 16) LOADB(nb, fs + 1);

            uint32_t c0 = (uint32_t)(s * 8 + t) ^ swz;
            uint32_t c1 = (uint32_t)(s * 8 + t + 4) ^ swz;
            int4 wa0 = *(const int4*)(ab + (R0    ) * 512 + (c0 << 4));
            int4 wa1 = *(const int4*)(ab + (R0 + 8) * 512 + (c0 << 4));
            int4 wa2 = *(const int4*)(ab + (R0    ) * 512 + (c1 << 4));
            int4 wa3 = *(const int4*)(ab + (R0 + 8) * 512 + (c1 << 4));
            uint32_t A0 = pack_s8(wa0);
            uint32_t A1 = pack_s8(wa1);
            uint32_t A2 = pack_s8(wa2);
            uint32_t A3 = pack_s8(wa3);

#pragma unroll
            for (int j = 0; j < 8; j++)
                imma16832(acc[j], A0, A1, A2, A3, cb[j].x, cb[j].y);

#pragma unroll
            for (int j = 0; j < 8; j++) cb[j] = nb[j];
        }

        __syncthreads();                                // buffer fully consumed
        if (ms + 2 < MEGA) ISSUE(ms + 2);
    }

#undef ISSUE
#undef LOADB

    // Epilogue: out = S0*plane0 (j<4) + S1*plane1 (j+4); store f32 partials.
    float* pk = g_partial + (size_t)blockIdx.y * OUT_F * BATCH;
    const int rg = rowbase + warp * 16 + g;
#pragma unroll
    for (int j = 0; j < 4; j++) {
        const int n0 = 8 * j + 2 * t;
        float2 v0, v1;
        v0.x = S0 * (float)acc[j][0] + S1 * (float)acc[j + 4][0];
        v0.y = S0 * (float)acc[j][1] + S1 * (float)acc[j + 4][1];
        v1.x = S0 * (float)acc[j][2] + S1 * (float)acc[j + 4][2];
        v1.y = S0 * (float)acc[j][3] + S1 * (float)acc[j + 4][3];
        *(float2*)(pk + (size_t)rg * BATCH + n0)       = v0;
        *(float2*)(pk + (size_t)(rg + 8) * BATCH + n0) = v1;
    }
}

// ---- Kernel 3: reduce k-splits, apply softplus scale + bias -----------------
__global__ void reduce_kernel(const float* __restrict__ log_scale,
                              const float* __restrict__ bias,
                              float* __restrict__ out) {
    int g  = blockIdx.x * blockDim.x + threadIdx.x;
    int o  = g >> 3;
    int bq = g & 7;

    const float4* __restrict__ base = (const float4*)g_partial;
    float4 s = make_float4(0.f, 0.f, 0.f, 0.f);
#pragma unroll
    for (int ky = 0; ky < KSPLIT; ky++) {
        float4 p = base[((size_t)ky * OUT_F + o) * (BATCH / 4) + bq];
        s.x += p.x; s.y += p.y; s.z += p.z; s.w += p.w;
    }

    float ls = log_scale[o];
    float sp = (ls > 20.0f) ? ls : log1pf(expf(ls));
    float sc = fmaxf(sp, 1e-4f);
    float bi = bias[o];

    int b0 = bq << 2;
    out[(size_t)(b0 + 0) * OUT_F + o] = fmaf(sc, s.x, bi);
    out[(size_t)(b0 + 1) * OUT_F + o] = fmaf(sc, s.y, bi);
    out[(size_t)(b0 + 2) * OUT_F + o] = fmaf(sc, s.z, bi);
    out[(size_t)(b0 + 3) * OUT_F + o] = fmaf(sc, s.w, bi);
}

// ---- Launch ------------------------------------------------------------------
extern "C" void kernel_launch(void* const* d_in, const int* in_sizes, int n_in,
                              void* d_out, int out_size) {
    const float* x  = nullptr;
    const int*   W  = nullptr;
    const float* ls = nullptr;
    const float* bi = nullptr;
    for (int i = 0; i < n_in; i++) {
        long long sz = in_sizes[i];
        if (sz == (long long)OUT_F * IN_F)      W = (const int*)d_in[i];
        else if (sz == (long long)BATCH * IN_F) x = (const float*)d_in[i];
        else if (sz == OUT_F) {
            if (!ls) ls = (const float*)d_in[i];
            else     bi = (const float*)d_in[i];
        }
    }
    float* out = (float*)d_out;

    cudaFuncSetAttribute(gemm_kernel, cudaFuncAttributeMaxDynamicSharedMemorySize,
                         SMEM_TOTAL);

    xprep_kernel<<<(BATCH * IN_F / 4) / 128, 128>>>(x);

    dim3 grid(OUT_F / MTILE, KSPLIT);            // (128, 16) = 2048 CTAs
    gemm_kernel<<<grid, THREADS, SMEM_TOTAL>>>(W);

    reduce_kernel<<<(OUT_F * BATCH / 4) / 256, 256>>>(ls, bi, out);
}